// round 2
// baseline (speedup 1.0000x reference)
#include <cuda_runtime.h>
#include <cuda_bf16.h>

// Problem constants
#define Bsz 2
#define Sq  2048
#define Dm  1024
#define Hn  16
#define HD  64
// derived
#define BH  (Bsz*Hn)                 // 32
#define TOK (Bsz*Sq)                 // 4096 rows
#define OUT_ATTN ((long long)Bsz*Sq*Dm)            // 4,194,304
#define OUT_W    ((long long)Bsz*Hn*Sq*Sq)         // 134,217,728

// ---------------------------------------------------------------------------
// Scratch (static device allocations are the sanctioned workaround).
// 4 x 16 MB = 64 MB total.
// ---------------------------------------------------------------------------
__device__ float g_Q[TOK * Dm];
__device__ float g_K[TOK * Dm];
__device__ float g_V[TOK * Dm];
__device__ float g_O[TOK * Dm];

// ---------------------------------------------------------------------------
// GEMM (NT): C[M,N] = alpha * A[M,K] @ B[N,K]^T, row-major, lda/ldb/ldc strides.
// Batched over blockIdx.z with (b,h)-style offsets: z = b*16 + h.
// BM=BN=128, BK=16, 256 threads, 8x8 accumulators per thread.
// ---------------------------------------------------------------------------
__global__ __launch_bounds__(256) void gemm_nt_kernel(
    const float* __restrict__ A, int lda, long long sAb, long long sAh,
    const float* __restrict__ Bm, int ldb, long long sBb, long long sBh,
    float* __restrict__ C, int ldc, long long sCb, long long sCh,
    int K, float alpha)
{
    const int z = blockIdx.z;
    const int zb = z >> 4, zh = z & 15;
    A  += (long long)zb * sAb + (long long)zh * sAh;
    Bm += (long long)zb * sBb + (long long)zh * sBh;
    C  += (long long)zb * sCb + (long long)zh * sCh;

    __shared__ float As[16][128];
    __shared__ float Bs[16][128];

    const int tid = threadIdx.x;
    const int tx = tid & 15;          // 0..15 -> 8 output cols each
    const int ty = tid >> 4;          // 0..15 -> 8 output rows each
    const int bm = blockIdx.y * 128;
    const int bn = blockIdx.x * 128;

    // Global->shared loader mapping: each thread loads 8 consecutive K-floats
    const int li = tid * 8;
    const int lm = li >> 4;           // row within tile (0..127)
    const int lk = li & 15;           // 0 or 8

    const float* Aptr = A  + (long long)(bm + lm) * lda + lk;
    const float* Bptr = Bm + (long long)(bn + lm) * ldb + lk;

    float acc[8][8];
#pragma unroll
    for (int i = 0; i < 8; i++)
#pragma unroll
        for (int j = 0; j < 8; j++) acc[i][j] = 0.f;

    for (int k0 = 0; k0 < K; k0 += 16) {
        float4 a0 = *(const float4*)(Aptr + k0);
        float4 a1 = *(const float4*)(Aptr + k0 + 4);
        float4 b0 = *(const float4*)(Bptr + k0);
        float4 b1 = *(const float4*)(Bptr + k0 + 4);

        As[lk + 0][lm] = a0.x; As[lk + 1][lm] = a0.y;
        As[lk + 2][lm] = a0.z; As[lk + 3][lm] = a0.w;
        As[lk + 4][lm] = a1.x; As[lk + 5][lm] = a1.y;
        As[lk + 6][lm] = a1.z; As[lk + 7][lm] = a1.w;

        Bs[lk + 0][lm] = b0.x; Bs[lk + 1][lm] = b0.y;
        Bs[lk + 2][lm] = b0.z; Bs[lk + 3][lm] = b0.w;
        Bs[lk + 4][lm] = b1.x; Bs[lk + 5][lm] = b1.y;
        Bs[lk + 6][lm] = b1.z; Bs[lk + 7][lm] = b1.w;

        __syncthreads();

#pragma unroll
        for (int kk = 0; kk < 16; kk++) {
            float4 a0v = *(const float4*)&As[kk][ty * 8];
            float4 a1v = *(const float4*)&As[kk][ty * 8 + 4];
            float4 b0v = *(const float4*)&Bs[kk][tx * 8];
            float4 b1v = *(const float4*)&Bs[kk][tx * 8 + 4];
            float a[8] = {a0v.x, a0v.y, a0v.z, a0v.w, a1v.x, a1v.y, a1v.z, a1v.w};
            float b[8] = {b0v.x, b0v.y, b0v.z, b0v.w, b1v.x, b1v.y, b1v.z, b1v.w};
#pragma unroll
            for (int i = 0; i < 8; i++)
#pragma unroll
                for (int j = 0; j < 8; j++)
                    acc[i][j] = fmaf(a[i], b[j], acc[i][j]);
        }
        __syncthreads();
    }

#pragma unroll
    for (int i = 0; i < 8; i++) {
        float* crow = C + (long long)(bm + ty * 8 + i) * ldc + bn + tx * 8;
#pragma unroll
        for (int j = 0; j < 8; j++) crow[j] = alpha * acc[i][j];
    }
}

// ---------------------------------------------------------------------------
// GEMM (NN): C[M,N=64] = A[M,K] @ B[K,N], used for P @ V_h.
// BM=128, BN=64, BK=16, 256 threads, 8x4 accumulators.
// ---------------------------------------------------------------------------
__global__ __launch_bounds__(256) void gemm_nn_kernel(
    const float* __restrict__ A, int lda, long long sAz,
    const float* __restrict__ Bm, int ldb, long long sBb, long long sBh,
    float* __restrict__ C, int ldc, long long sCb, long long sCh,
    int K)
{
    const int z = blockIdx.z;
    const int zb = z >> 4, zh = z & 15;
    A  += (long long)z * sAz;
    Bm += (long long)zb * sBb + (long long)zh * sBh;
    C  += (long long)zb * sCb + (long long)zh * sCh;

    __shared__ float As[16][128];
    __shared__ float Bs[16][64];

    const int tid = threadIdx.x;
    const int tx = tid & 15;          // 4 cols each
    const int ty = tid >> 4;          // 8 rows each
    const int bm = blockIdx.y * 128;

    const int li = tid * 8;
    const int lm = li >> 4;
    const int lk = li & 15;
    const float* Aptr = A + (long long)(bm + lm) * lda + lk;

    const int bi = tid * 4;
    const int bk = bi >> 6;           // 0..15
    const int bn = bi & 63;
    const float* Bptr = Bm + (long long)bk * ldb + bn;

    float acc[8][4];
#pragma unroll
    for (int i = 0; i < 8; i++)
#pragma unroll
        for (int j = 0; j < 4; j++) acc[i][j] = 0.f;

    for (int k0 = 0; k0 < K; k0 += 16) {
        float4 a0 = *(const float4*)(Aptr + k0);
        float4 a1 = *(const float4*)(Aptr + k0 + 4);
        float4 bv = *(const float4*)(Bptr + (long long)k0 * ldb);

        As[lk + 0][lm] = a0.x; As[lk + 1][lm] = a0.y;
        As[lk + 2][lm] = a0.z; As[lk + 3][lm] = a0.w;
        As[lk + 4][lm] = a1.x; As[lk + 5][lm] = a1.y;
        As[lk + 6][lm] = a1.z; As[lk + 7][lm] = a1.w;

        *(float4*)&Bs[bk][bn] = bv;

        __syncthreads();

#pragma unroll
        for (int kk = 0; kk < 16; kk++) {
            float4 a0v = *(const float4*)&As[kk][ty * 8];
            float4 a1v = *(const float4*)&As[kk][ty * 8 + 4];
            float4 bv2 = *(const float4*)&Bs[kk][tx * 4];
            float a[8] = {a0v.x, a0v.y, a0v.z, a0v.w, a1v.x, a1v.y, a1v.z, a1v.w};
            float b[4] = {bv2.x, bv2.y, bv2.z, bv2.w};
#pragma unroll
            for (int i = 0; i < 8; i++)
#pragma unroll
                for (int j = 0; j < 4; j++)
                    acc[i][j] = fmaf(a[i], b[j], acc[i][j]);
        }
        __syncthreads();
    }

#pragma unroll
    for (int i = 0; i < 8; i++) {
        float* crow = C + (long long)(bm + ty * 8 + i) * ldc + tx * 4;
#pragma unroll
        for (int j = 0; j < 4; j++) crow[j] = acc[i][j];
    }
}

// ---------------------------------------------------------------------------
// Softmax over rows of P (in place), adding broadcasted attention mask first.
// One 256-thread block per row of 2048 floats. Row id = ((b*H+h)*S + q).
// ---------------------------------------------------------------------------
__global__ __launch_bounds__(256) void softmax_kernel(
    float* __restrict__ P, const float* __restrict__ mask)
{
    const long long row = blockIdx.x;
    const int q = (int)(row & (Sq - 1));
    const int b = (int)(row >> 15);          // row / (H*S) with H*S = 32768
    float* p = P + row * Sq;
    const float* m = mask + ((long long)b * Sq + q) * Sq;

    const int t = threadIdx.x;
    const int lane = t & 31, wid = t >> 5;
    __shared__ float red[8];

    float v[8];
    float mx = -3.402823466e38f;
#pragma unroll
    for (int j = 0; j < 8; j++) {
        int idx = j * 256 + t;
        v[j] = p[idx] + m[idx];
        mx = fmaxf(mx, v[j]);
    }
    // block max
#pragma unroll
    for (int o = 16; o > 0; o >>= 1) mx = fmaxf(mx, __shfl_xor_sync(0xffffffffu, mx, o));
    if (lane == 0) red[wid] = mx;
    __syncthreads();
    mx = red[0];
#pragma unroll
    for (int w = 1; w < 8; w++) mx = fmaxf(mx, red[w]);
    __syncthreads();

    float s = 0.f;
#pragma unroll
    for (int j = 0; j < 8; j++) {
        v[j] = __expf(v[j] - mx);
        s += v[j];
    }
#pragma unroll
    for (int o = 16; o > 0; o >>= 1) s += __shfl_xor_sync(0xffffffffu, s, o);
    if (lane == 0) red[wid] = s;
    __syncthreads();
    s = red[0];
#pragma unroll
    for (int w = 1; w < 8; w++) s += red[w];

    const float inv = 1.0f / s;
#pragma unroll
    for (int j = 0; j < 8; j++) p[j * 256 + t] = v[j] * inv;
}

// ---------------------------------------------------------------------------
// Host launcher
// ---------------------------------------------------------------------------
extern "C" void kernel_launch(void* const* d_in, const int* in_sizes, int n_in,
                              void* d_out, int out_size)
{
    const float* q    = (const float*)d_in[0];
    const float* k    = (const float*)d_in[1];
    const float* v    = (const float*)d_in[2];
    const float* mask = (const float*)d_in[3];
    const float* Wq   = (const float*)d_in[4];
    const float* Wk   = (const float*)d_in[5];
    const float* Wv   = (const float*)d_in[6];
    const float* Wo   = (const float*)d_in[7];
    float* out = (float*)d_out;

    void *pQ, *pK, *pV, *pO;
    cudaGetSymbolAddress(&pQ, g_Q);
    cudaGetSymbolAddress(&pK, g_K);
    cudaGetSymbolAddress(&pV, g_V);
    cudaGetSymbolAddress(&pO, g_O);

    float* Qb = (float*)pQ;
    float* Kb = (float*)pK;
    float* Vb = (float*)pV;
    float* Ob = (float*)pO;

    // attn_weights live right after attn_output in d_out (tuple output).
    float* P = out + OUT_ATTN;

    const dim3 blk(256);

    // 1) Projections: X @ W^T   (M=4096, N=1024, K=1024)
    {
        dim3 grid(Dm / 128, TOK / 128, 1);
        gemm_nt_kernel<<<grid, blk>>>(q, Dm, 0, 0, Wq, Dm, 0, 0,
                                      Qb, Dm, 0, 0, Dm, 1.0f);
        gemm_nt_kernel<<<grid, blk>>>(k, Dm, 0, 0, Wk, Dm, 0, 0,
                                      Kb, Dm, 0, 0, Dm, 1.0f);
        gemm_nt_kernel<<<grid, blk>>>(v, Dm, 0, 0, Wv, Dm, 0, 0,
                                      Vb, Dm, 0, 0, Dm, 1.0f);
    }

    // 2) Scores: P = (Q_h @ K_h^T) / 8 per (b,h).  M=N=2048, K=64.
    {
        dim3 grid(Sq / 128, Sq / 128, BH);
        gemm_nt_kernel<<<grid, blk>>>(
            Qb, Dm, (long long)Sq * Dm, HD,
            Kb, Dm, (long long)Sq * Dm, HD,
            P,  Sq, (long long)Hn * Sq * Sq, (long long)Sq * Sq,
            HD, 0.125f);
    }

    // 3) Softmax rows (in place, adds mask)
    softmax_kernel<<<BH * Sq, blk>>>(P, mask);

    // 4) O_h = P_h @ V_h, written into merged-head layout [B*S, D].
    {
        dim3 grid(1, Sq / 128, BH);
        gemm_nn_kernel<<<grid, blk>>>(
            P,  Sq, (long long)Sq * Sq,
            Vb, Dm, (long long)Sq * Dm, HD,
            Ob, Dm, (long long)Sq * Dm, HD,
            Sq);
    }

    // 5) attn_output = O @ Wo^T  -> first OUT_ATTN floats of d_out
    {
        dim3 grid(Dm / 128, TOK / 128, 1);
        gemm_nt_kernel<<<grid, blk>>>(Ob, Dm, 0, 0, Wo, Dm, 0, 0,
                                      out, Dm, 0, 0, Dm, 1.0f);
    }
}